// round 16
// baseline (speedup 1.0000x reference)
#include <cuda_runtime.h>
#include <cstdint>

// SLayer: out[b,n] = sum_p exp(-(s0*(c0-x)^2 + s1*(c1-y)^2)) * mask[b,p]
// B=64, P=16384, N=64, D=2
constexpr int B_ = 64;
constexpr int P_ = 16384;
constexpr int N_ = 64;
constexpr int JP = 512;                // points per job tile
constexpr int NTILES = P_ / JP;        // 32 half-tiles per batch
constexpr int NJOBS = B_ * NTILES;     // 2048 jobs per z-half
constexpr int GB = 592;                // 148 SMs * 4 blocks = ONE wave
constexpr int BSLOTS = GB / 2;         // 296 block slots per z-half
constexpr int NPW = 4;                 // n per warp; 8 warps * 4 = 32, z covers 2 halves
constexpr int NPAIR = NPW / 2;         // 2 packed pairs

__global__ void zero_out_kernel(float* out) {
    out[blockIdx.x * blockDim.x + threadIdx.x] = 0.0f;
}

__device__ __forceinline__ uint64_t pack2(float lo, float hi) {
    uint64_t d;
    asm("mov.b64 %0, {%1, %2};" : "=l"(d) : "f"(lo), "f"(hi));
    return d;
}

__device__ __forceinline__ void unpack2(float& lo, float& hi, uint64_t v) {
    asm("mov.b64 {%0, %1}, %2;" : "=f"(lo), "=f"(hi) : "l"(v));
}

__device__ __forceinline__ uint64_t fma2(uint64_t a, uint64_t b, uint64_t c) {
    uint64_t d;
    asm("fma.rn.f32x2 %0, %1, %2, %3;" : "=l"(d) : "l"(a), "l"(b), "l"(c));
    return d;
}

__device__ __forceinline__ uint64_t mul2(uint64_t a, uint64_t b) {
    uint64_t d;
    asm("mul.rn.f32x2 %0, %1, %2;" : "=l"(d) : "l"(a), "l"(b));
    return d;
}

__device__ __forceinline__ uint32_t ex2_f16x2_from_f32(float lo, float hi) {
    uint32_t h, r;
    asm("cvt.rn.f16x2.f32 %0, %1, %2;" : "=r"(h) : "f"(hi), "f"(lo));
    asm("ex2.approx.f16x2 %0, %1;" : "=r"(r) : "r"(h));
    return r;
}

__device__ __forceinline__ uint32_t hfma2(uint32_t a, uint32_t b, uint32_t c) {
    uint32_t d;
    asm("fma.rn.f16x2 %0, %1, %2, %3;" : "=r"(d) : "r"(a), "r"(b), "r"(c));
    return d;
}

__device__ __forceinline__ uint32_t f32_to_h2(float v) {
    uint32_t r;
    asm("cvt.rn.f16x2.f32 %0, %1, %1;" : "=r"(r) : "f"(v));
    return r;
}

__device__ __forceinline__ void h2_to_f32(float& lo, float& hi, uint32_t w) {
    uint16_t h0, h1;
    asm("mov.b32 {%0, %1}, %2;" : "=h"(h0), "=h"(h1) : "r"(w));
    asm("cvt.f32.f16 %0, %1;" : "=f"(lo) : "h"(h0));
    asm("cvt.f32.f16 %0, %1;" : "=f"(hi) : "h"(h1));
}

__device__ __forceinline__ void cp16(uint32_t dst, const void* src) {
    asm volatile("cp.async.cg.shared.global [%0], [%1], 16;" :: "r"(dst), "l"(src));
}

__global__ __launch_bounds__(256, 4)
void rbf_pool_kernel(const float* __restrict__ batch,
                     const float* __restrict__ mask,
                     const float* __restrict__ centers,
                     const float* __restrict__ sharp,
                     float* __restrict__ out) {
    __shared__ __align__(16) float2 spts[2][JP];   // 2 x 4KB
    __shared__ __align__(16) float  smsk[2][JP];   // 2 x 2KB

    const int tid   = threadIdx.x;
    const int warp  = tid >> 5;
    const int lane  = tid & 31;
    const int z     = blockIdx.x & 1;
    const int bslot = blockIdx.x >> 1;             // 0..295
    const int n0    = z * 32 + warp * NPW;
    const int njobs = 1 + (NJOBS - 1 - bslot) / BSLOTS;  // 6 or 7

    // ---- per-warp packed constants (expanded quadratic, L folded) ----
    const float L = -1.4426950408889634f;
    uint64_t A0p[NPAIR], A1p[NPAIR], Bxp[NPAIR], Byp[NPAIR], Cp[NPAIR];
#pragma unroll
    for (int j = 0; j < NPAIR; j++) {
        float a0[2], a1[2], bx[2], by[2], cc[2];
#pragma unroll
        for (int h = 0; h < 2; h++) {
            const int n = n0 + 2 * j + h;
            const float c0 = centers[n * 2 + 0];
            const float c1 = centers[n * 2 + 1];
            const float s0 = sharp[n * 2 + 0];
            const float s1 = sharp[n * 2 + 1];
            a0[h] = L * s0;
            a1[h] = L * s1;
            bx[h] = -2.0f * L * s0 * c0;
            by[h] = -2.0f * L * s1 * c1;
            cc[h] = L * (s0 * c0 * c0 + s1 * c1 * c1);
        }
        A0p[j] = pack2(a0[0], a0[1]);
        A1p[j] = pack2(a1[0], a1[1]);
        Bxp[j] = pack2(bx[0], bx[1]);
        Byp[j] = pack2(by[0], by[1]);
        Cp[j]  = pack2(cc[0], cc[1]);
    }

    // ---- staging helper (lambda-free, inline) ----
    auto stage = [&](int jid, int buf) {
        const int jb = jid >> 5;           // batch
        const int ht = jid & 31;           // half-tile
        const size_t off = (size_t)jb * P_ + (size_t)ht * JP;
        const char* psrc = (const char*)batch + off * 8;   // 4KB
        const char* msrc = (const char*)mask  + off * 4;   // 2KB
        const uint32_t pdst = (uint32_t)__cvta_generic_to_shared(&spts[buf][0]);
        const uint32_t mdst = (uint32_t)__cvta_generic_to_shared(&smsk[buf][0]);
        cp16(pdst + tid * 16, psrc + tid * 16);            // 256 thr x 16B = 4KB
        if (tid < 128)
            cp16(mdst + tid * 16, msrc + tid * 16);        // 128 thr x 16B = 2KB
        asm volatile("cp.async.commit_group;");
    };

    stage(bslot, 0);

    for (int k = 0; k < njobs; k++) {
        const bool has_next = (k + 1 < njobs);
        if (has_next) stage(bslot + (k + 1) * BSLOTS, (k + 1) & 1);

        if (has_next) asm volatile("cp.async.wait_group 1;");
        else          asm volatile("cp.async.wait_group 0;");
        __syncthreads();

        const int cur = k & 1;
        const int jid = bslot + k * BSLOTS;
        const int b   = jid >> 5;
        const float2* sp = spts[cur];
        const float*  sm = smsk[cur];

        float jacc[NPW];
#pragma unroll
        for (int i = 0; i < NPW; i++) jacc[i] = 0.0f;

        // 16 points per lane = 8 two-point iterations = 2 chunks of 4 iters
#pragma unroll
        for (int c = 0; c < 2; c++) {
            uint32_t hacc[NPAIR];
#pragma unroll
            for (int j = 0; j < NPAIR; j++) hacc[j] = 0u;
#pragma unroll
            for (int u = 0; u < 4; u++) {
                const int idx = (c * 4 + u) * 64 + 2 * lane;
                const float4 pq = *reinterpret_cast<const float4*>(&sp[idx]); // 2 pts
                const float2 mq = *reinterpret_cast<const float2*>(&sm[idx]); // 2 masks
                // point 0
                const uint64_t xb0  = pack2(pq.x, pq.x);
                const uint64_t yb0  = pack2(pq.y, pq.y);
                const uint64_t x2b0 = mul2(xb0, xb0);
                const uint64_t y2b0 = mul2(yb0, yb0);
                const uint32_t mh0  = f32_to_h2(mq.x);
                // point 1
                const uint64_t xb1  = pack2(pq.z, pq.z);
                const uint64_t yb1  = pack2(pq.w, pq.w);
                const uint64_t x2b1 = mul2(xb1, xb1);
                const uint64_t y2b1 = mul2(yb1, yb1);
                const uint32_t mh1  = f32_to_h2(mq.y);
#pragma unroll
                for (int j = 0; j < NPAIR; j++) {
                    uint64_t e0 = fma2(A0p[j], x2b0, Cp[j]);
                    e0 = fma2(A1p[j], y2b0, e0);
                    e0 = fma2(Bxp[j], xb0, e0);
                    e0 = fma2(Byp[j], yb0, e0);
                    uint64_t e1 = fma2(A0p[j], x2b1, Cp[j]);
                    e1 = fma2(A1p[j], y2b1, e1);
                    e1 = fma2(Bxp[j], xb1, e1);
                    e1 = fma2(Byp[j], yb1, e1);
                    float e0lo, e0hi, e1lo, e1hi;
                    unpack2(e0lo, e0hi, e0);
                    unpack2(e1lo, e1hi, e1);
                    const uint32_t w0 = ex2_f16x2_from_f32(e0lo, e0hi);
                    const uint32_t w1 = ex2_f16x2_from_f32(e1lo, e1hi);
                    hacc[j] = hfma2(w0, mh0, hacc[j]);
                    hacc[j] = hfma2(w1, mh1, hacc[j]);
                }
            }
#pragma unroll
            for (int j = 0; j < NPAIR; j++) {
                float flo, fhi;
                h2_to_f32(flo, fhi, hacc[j]);
                jacc[2 * j]     += flo;
                jacc[2 * j + 1] += fhi;
            }
        }

        // warp tree-reduce, lane 0 commits this job's partials
#pragma unroll
        for (int i = 0; i < NPW; i++) {
            float v = jacc[i];
#pragma unroll
            for (int o = 16; o > 0; o >>= 1)
                v += __shfl_xor_sync(0xFFFFFFFFu, v, o);
            if (lane == 0)
                atomicAdd(&out[b * N_ + n0 + i], v);
        }
        __syncthreads();   // all reads of buf[cur] done before it is restaged
    }
}

extern "C" void kernel_launch(void* const* d_in, const int* in_sizes, int n_in,
                              void* d_out, int out_size) {
    const float* batch   = (const float*)d_in[0];  // [64,16384,2]
    const float* mask    = (const float*)d_in[1];  // [64,16384]
    const float* centers = (const float*)d_in[2];  // [64,2]
    const float* sharp   = (const float*)d_in[3];  // [64,2]
    float* out = (float*)d_out;                    // [64,64]

    zero_out_kernel<<<16, 256>>>(out);             // 4096 elems
    rbf_pool_kernel<<<GB, 256>>>(batch, mask, centers, sharp, out);
}